// round 14
// baseline (speedup 1.0000x reference)
#include <cuda_runtime.h>
#include <math.h>

typedef unsigned long long u64;

// ---------------- packed f32x2 helpers (sm_103a) ----------------
__device__ __forceinline__ u64 pack2(float a, float b){ u64 r; asm("mov.b64 %0,{%1,%2};":"=l"(r):"f"(a),"f"(b)); return r; }
__device__ __forceinline__ u64 pack1(float a){ u64 r; asm("mov.b64 %0,{%1,%1};":"=l"(r):"f"(a)); return r; }
__device__ __forceinline__ void unpack2(u64 v, float& a, float& b){ asm("mov.b64 {%0,%1},%2;":"=f"(a),"=f"(b):"l"(v)); }
__device__ __forceinline__ u64 fma2(u64 a,u64 b,u64 c){ u64 d; asm("fma.rn.f32x2 %0,%1,%2,%3;":"=l"(d):"l"(a),"l"(b),"l"(c)); return d; }
__device__ __forceinline__ float hadd2(u64 v){ float a,b; unpack2(v,a,b); return a+b; }

// HW tanh (MUFU.TANH): verified rel_err ~1.9e-6 end-to-end (R11)
__device__ __forceinline__ float tanh_hw(float x){
    float y; asm("tanh.approx.f32 %0, %1;" : "=f"(y) : "f"(x)); return y;
}
__device__ __forceinline__ float sig_hw(float x){
    return fmaf(0.5f, tanh_hw(0.5f * x), 0.5f);
}
// tanh-form gelu with HW tanh
__device__ __forceinline__ float gelu1(float v){
    float u = (v * 0.7978845608028654f) * fmaf(0.044715f * v, v, 1.0f);
    float hv = 0.5f * v;
    return fmaf(hv, tanh_hw(u), hv);
}

// ---------------- folded-weight scratch ----------------
__device__ float g_A[1024];   // (wq^T wk) / sqrt(32)
__device__ float g_W1[1024];  // w_ih @ Wo @ wv
__device__ float g_r[32];     // (wk^T bq) / sqrt(32)
__device__ float g_c1[32];    // w_ih @ (Wo bv + bo) + b_ih + b_hh

// ---------------- prep kernel ----------------
__global__ void prep_kernel(const float* __restrict__ ipw, const float* __restrict__ ipb,
                            const float* __restrict__ opw, const float* __restrict__ opb,
                            const float* __restrict__ wih, const float* __restrict__ bih,
                            const float* __restrict__ bhh)
{
    __shared__ float T[1024];
    __shared__ float t2[32];
    const float inv = 0.17677669529663688f;
    int tid = threadIdx.x;
    int i = tid >> 5, j = tid & 31;
    const float* wq = ipw;
    const float* wk = ipw + 1024;
    const float* wv = ipw + 2048;

    float a = 0.f, t = 0.f;
    #pragma unroll 8
    for (int m = 0; m < 32; m++){
        a += wq[m*32 + i] * wk[m*32 + j];
        t += opw[i*32 + m] * wv[m*32 + j];
    }
    g_A[i*32 + j] = a * inv;
    T[i*32 + j] = t;

    if (i == 0){
        float rr = 0.f, tt = 0.f;
        #pragma unroll 8
        for (int m = 0; m < 32; m++){
            rr += ipb[m] * wk[m*32 + j];
            tt += opw[j*32 + m] * ipb[64 + m];
        }
        g_r[j] = rr * inv;
        t2[j] = tt + opb[j];
    }
    __syncthreads();

    float w1 = 0.f;
    #pragma unroll 8
    for (int m = 0; m < 32; m++)
        w1 += wih[i*32 + m] * T[m*32 + j];
    g_W1[i*32 + j] = w1;

    if (i == 0){
        float c = 0.f;
        #pragma unroll 8
        for (int m = 0; m < 32; m++)
            c += wih[j*32 + m] * t2[m];
        g_c1[j] = c + bih[j] + bhh[j];
    }
}

// ---------------- fused main: R11 body; 96-thr blocks, 3 blocks/SM (cap 227) ----------------
__global__ __launch_bounds__(96, 3) void fused_kernel(
    const float* __restrict__ x,
    const float* __restrict__ embw, const float* __restrict__ embb,
    const float* __restrict__ whh,
    const float* __restrict__ decw, const float* __restrict__ decb,
    const float* __restrict__ outw, const float* __restrict__ outb,
    float* __restrict__ out, int B)
{
    __shared__ __align__(16) float sA [1024];
    __shared__ __align__(16) float sW1[1024];
    __shared__ __align__(16) float sWh[1024];
    __shared__ __align__(16) float sDec[160];
    __shared__ __align__(16) float sR[32];
    __shared__ __align__(16) float sEmbT[160];   // transposed: [k][l]
    __shared__ __align__(16) float sC1[32];
    __shared__ __align__(16) float sEmbB[32];
    __shared__ float sDecB[8];
    __shared__ float sOw[16];
    __shared__ float sOb[4];

    const int tid = threadIdx.x;
    for (int i = tid; i < 1024; i += 96){
        sA[i]  = g_A[i];
        sW1[i] = g_W1[i];
        sWh[i] = whh[i];
    }
    for (int i = tid; i < 160; i += 96){
        sDec[i] = decw[i];
        int l = i / 5, k = i % 5;
        sEmbT[k*32 + l] = embw[i];
    }
    if (tid < 32){ sC1[tid] = g_c1[tid]; sR[tid] = g_r[tid]; sEmbB[tid] = embb[tid]; }
    if (tid < 15) sOw[tid] = outw[tid];
    if (tid < 5)  sDecB[tid] = decb[tid];
    if (tid < 3)  sOb[tid] = outb[tid];
    __syncthreads();

    int r = blockIdx.x * 96 + tid;
    if (r >= B) return;

    // ---- load x row (10 floats, 8B aligned) ----
    float xv[10];
    {
        const float2* xp = reinterpret_cast<const float2*>(x + (long long)r*10);
        #pragma unroll
        for (int k = 0; k < 5; k++){ float2 t = xp[k]; xv[2*k] = t.x; xv[2*k+1] = t.y; }
    }
    u64 xp0[5], xp1[5];
    #pragma unroll
    for (int k = 0; k < 5; k++){ xp0[k] = pack1(xv[k]); xp1[k] = pack1(xv[5+k]); }

    // ---- embedding (packed along output dims) ----
    u64 e0p[16], dep[16];
    const u64* ebp = reinterpret_cast<const u64*>(sEmbB);
    #pragma unroll
    for (int i = 0; i < 16; i++){
        u64 a0 = ebp[i], a1 = a0;
        #pragma unroll
        for (int k = 0; k < 5; k++){
            u64 w = *reinterpret_cast<const u64*>(sEmbT + k*32 + 2*i);
            a0 = fma2(w, xp0[k], a0);
            a1 = fma2(w, xp1[k], a1);
        }
        float v00, v10, v01, v11;
        unpack2(a0, v00, v10);
        unpack2(a1, v01, v11);
        float g00 = gelu1(v00), g10 = gelu1(v10);
        float g01 = gelu1(v01), g11 = gelu1(v11);
        e0p[i] = pack2(g00, g10);
        dep[i] = pack2(g01 - g00, g11 - g10);
    }

    // ---- attention: delta0 = e0.(A de) + r.de ; delta1 = delta0 + de.(A de) ----
    u64 dE = 0ull, dD = 0ull, dR = 0ull;
    const u64* rp = reinterpret_cast<const u64*>(sR);
    #pragma unroll
    for (int i = 0; i < 16; i++){
        const ulonglong2* rowA0 = reinterpret_cast<const ulonglong2*>(sA + (2*i)*32);
        const ulonglong2* rowA1 = reinterpret_cast<const ulonglong2*>(sA + (2*i+1)*32);
        u64 w0 = 0ull, w1 = 0ull;
        #pragma unroll
        for (int c = 0; c < 8; c++){
            ulonglong2 v0 = rowA0[c], v1 = rowA1[c];
            w0 = fma2(v0.x, dep[2*c],   w0);
            w0 = fma2(v0.y, dep[2*c+1], w0);
            w1 = fma2(v1.x, dep[2*c],   w1);
            w1 = fma2(v1.y, dep[2*c+1], w1);
        }
        u64 wp = pack2(hadd2(w0), hadd2(w1));
        dE = fma2(e0p[i], wp, dE);
        dD = fma2(dep[i], wp, dD);
        dR = fma2(rp[i], dep[i], dR);
    }
    float d0 = hadd2(dE) + hadd2(dR);
    float d1 = d0 + hadd2(dD);
    float a01 = sig_hw(d0);
    float a11 = sig_hw(d1);
    u64 a01p = pack1(a01);
    u64 adp  = pack1(a11 - a01);

    // ---- m0 = e0 + a01*de (in place) ----
    #pragma unroll
    for (int i = 0; i < 16; i++) e0p[i] = fma2(a01p, dep[i], e0p[i]);

    // ---- h1 = tanh(W1 m0 + c1) ----
    u64 h1p[16];
    #pragma unroll
    for (int i = 0; i < 16; i++){
        const ulonglong2* r0w = reinterpret_cast<const ulonglong2*>(sW1 + (2*i)*32);
        const ulonglong2* r1w = reinterpret_cast<const ulonglong2*>(sW1 + (2*i+1)*32);
        u64 s0 = 0ull, s1 = 0ull;
        #pragma unroll
        for (int c = 0; c < 8; c++){
            ulonglong2 v0 = r0w[c], v1 = r1w[c];
            s0 = fma2(v0.x, e0p[2*c],   s0);
            s0 = fma2(v0.y, e0p[2*c+1], s0);
            s1 = fma2(v1.x, e0p[2*c],   s1);
            s1 = fma2(v1.y, e0p[2*c+1], s1);
        }
        float v0 = hadd2(s0) + sC1[2*i];
        float v1 = hadd2(s1) + sC1[2*i+1];
        h1p[i] = pack2(tanh_hw(v0), tanh_hw(v1));
    }

    // ---- m1 = m0 + (a11-a01)*de (in place) ----
    #pragma unroll
    for (int i = 0; i < 16; i++) e0p[i] = fma2(adp, dep[i], e0p[i]);

    // ---- h2 = tanh(W1 m1 + Wh h1 + c1); write into dep (register reuse) ----
    #pragma unroll
    for (int i = 0; i < 16; i++){
        const ulonglong2* rw0 = reinterpret_cast<const ulonglong2*>(sW1 + (2*i)*32);
        const ulonglong2* rw1 = reinterpret_cast<const ulonglong2*>(sW1 + (2*i+1)*32);
        const ulonglong2* rh0 = reinterpret_cast<const ulonglong2*>(sWh + (2*i)*32);
        const ulonglong2* rh1 = reinterpret_cast<const ulonglong2*>(sWh + (2*i+1)*32);
        u64 s0 = 0ull, s1 = 0ull, t0 = 0ull, t1 = 0ull;
        #pragma unroll
        for (int c = 0; c < 8; c++){
            ulonglong2 vw0 = rw0[c], vh0 = rh0[c];
            ulonglong2 vw1 = rw1[c], vh1 = rh1[c];
            s0 = fma2(vw0.x, e0p[2*c],   s0);
            s0 = fma2(vw0.y, e0p[2*c+1], s0);
            t0 = fma2(vh0.x, h1p[2*c],   t0);
            t0 = fma2(vh0.y, h1p[2*c+1], t0);
            s1 = fma2(vw1.x, e0p[2*c],   s1);
            s1 = fma2(vw1.y, e0p[2*c+1], s1);
            t1 = fma2(vh1.x, h1p[2*c],   t1);
            t1 = fma2(vh1.y, h1p[2*c+1], t1);
        }
        float v0 = hadd2(s0) + hadd2(t0) + sC1[2*i];
        float v1 = hadd2(s1) + hadd2(t1) + sC1[2*i+1];
        dep[i] = pack2(tanh_hw(v0), tanh_hw(v1));   // h2 -> dep
    }

    // ---- decode: d = gelu(Dec h2 + b) ; out = Ow d + ob ----
    float dv[5];
    #pragma unroll
    for (int j = 0; j < 5; j++){
        const ulonglong2* rd = reinterpret_cast<const ulonglong2*>(sDec + j*32);
        u64 acc = 0ull;
        #pragma unroll
        for (int c = 0; c < 8; c++){
            ulonglong2 v = rd[c];
            acc = fma2(v.x, dep[2*c],   acc);
            acc = fma2(v.y, dep[2*c+1], acc);
        }
        dv[j] = gelu1(hadd2(acc) + sDecB[j]);
    }
    #pragma unroll
    for (int o = 0; o < 3; o++){
        float acc = sOb[o];
        #pragma unroll
        for (int j = 0; j < 5; j++) acc = fmaf(sOw[o*5 + j], dv[j], acc);
        out[(long long)r*3 + o] = acc;
    }
}

// ---------------- launch ----------------
extern "C" void kernel_launch(void* const* d_in, const int* in_sizes, int n_in,
                              void* d_out, int out_size)
{
    const float* x      = (const float*)d_in[0];
    const float* embw   = (const float*)d_in[1];
    const float* embb   = (const float*)d_in[2];
    const float* ipw    = (const float*)d_in[3];
    const float* ipb    = (const float*)d_in[4];
    const float* opw    = (const float*)d_in[5];
    const float* opb    = (const float*)d_in[6];
    const float* wih    = (const float*)d_in[7];
    const float* bih    = (const float*)d_in[8];
    const float* whh    = (const float*)d_in[9];
    const float* bhh    = (const float*)d_in[10];
    const float* decw   = (const float*)d_in[11];
    const float* decb   = (const float*)d_in[12];
    const float* outw   = (const float*)d_in[13];
    const float* outb   = (const float*)d_in[14];
    float* out = (float*)d_out;

    int B = in_sizes[0] / 10;

    prep_kernel<<<1, 1024>>>(ipw, ipb, opw, opb, wih, bih, bhh);

    int blocks = (B + 95) / 96;
    fused_kernel<<<blocks, 96>>>(x, embw, embb, whh, decw, decb, outw, outb, out, B);
}

// round 15
// speedup vs baseline: 1.4694x; 1.4694x over previous
#include <cuda_runtime.h>
#include <math.h>

typedef unsigned long long u64;

// ---------------- packed f32x2 helpers (sm_103a) ----------------
__device__ __forceinline__ u64 pack2(float a, float b){ u64 r; asm("mov.b64 %0,{%1,%2};":"=l"(r):"f"(a),"f"(b)); return r; }
__device__ __forceinline__ u64 pack1(float a){ u64 r; asm("mov.b64 %0,{%1,%1};":"=l"(r):"f"(a)); return r; }
__device__ __forceinline__ void unpack2(u64 v, float& a, float& b){ asm("mov.b64 {%0,%1},%2;":"=f"(a),"=f"(b):"l"(v)); }
__device__ __forceinline__ u64 fma2(u64 a,u64 b,u64 c){ u64 d; asm("fma.rn.f32x2 %0,%1,%2,%3;":"=l"(d):"l"(a),"l"(b),"l"(c)); return d; }
__device__ __forceinline__ u64 add2(u64 a,u64 b){ u64 d; asm("add.rn.f32x2 %0,%1,%2;":"=l"(d):"l"(a),"l"(b)); return d; }
__device__ __forceinline__ float hadd2(u64 v){ float a,b; unpack2(v,a,b); return a+b; }

// HW tanh (MUFU.TANH): verified rel_err ~1.9e-6 end-to-end (R11)
__device__ __forceinline__ float tanh_hw(float x){
    float y; asm("tanh.approx.f32 %0, %1;" : "=f"(y) : "f"(x)); return y;
}
__device__ __forceinline__ float sig_hw(float x){
    return fmaf(0.5f, tanh_hw(0.5f * x), 0.5f);
}
// tanh-form gelu with HW tanh
__device__ __forceinline__ float gelu1(float v){
    float u = (v * 0.7978845608028654f) * fmaf(0.044715f * v, v, 1.0f);
    float hv = 0.5f * v;
    return fmaf(hv, tanh_hw(u), hv);
}

// ---------------- folded-weight scratch ----------------
__device__ float g_A[1024];   // (wq^T wk) / sqrt(32)
__device__ float g_W1[1024];  // w_ih @ Wo @ wv
__device__ float g_r[32];     // (wk^T bq) / sqrt(32)
__device__ float g_c1[32];    // w_ih @ (Wo bv + bo) + b_ih + b_hh

// ---------------- prep kernel ----------------
__global__ void prep_kernel(const float* __restrict__ ipw, const float* __restrict__ ipb,
                            const float* __restrict__ opw, const float* __restrict__ opb,
                            const float* __restrict__ wih, const float* __restrict__ bih,
                            const float* __restrict__ bhh)
{
    __shared__ float T[1024];
    __shared__ float t2[32];
    const float inv = 0.17677669529663688f;
    int tid = threadIdx.x;
    int i = tid >> 5, j = tid & 31;
    const float* wq = ipw;
    const float* wk = ipw + 1024;
    const float* wv = ipw + 2048;

    float a = 0.f, t = 0.f;
    #pragma unroll 8
    for (int m = 0; m < 32; m++){
        a += wq[m*32 + i] * wk[m*32 + j];
        t += opw[i*32 + m] * wv[m*32 + j];
    }
    g_A[i*32 + j] = a * inv;
    T[i*32 + j] = t;

    if (i == 0){
        float rr = 0.f, tt = 0.f;
        #pragma unroll 8
        for (int m = 0; m < 32; m++){
            rr += ipb[m] * wk[m*32 + j];
            tt += opw[j*32 + m] * ipb[64 + m];
        }
        g_r[j] = rr * inv;
        t2[j] = tt + opb[j];
    }
    __syncthreads();

    float w1 = 0.f;
    #pragma unroll 8
    for (int m = 0; m < 32; m++)
        w1 += wih[i*32 + m] * T[m*32 + j];
    g_W1[i*32 + j] = w1;

    if (i == 0){
        float c = 0.f;
        #pragma unroll 8
        for (int m = 0; m < 32; m++)
            c += wih[j*32 + m] * t2[m];
        g_c1[j] = c + bih[j] + bhh[j];
    }
}

// ---------------- fused main: R11 structure + split accumulator trees ----------------
__global__ __launch_bounds__(256) void fused_kernel(
    const float* __restrict__ x,
    const float* __restrict__ embw, const float* __restrict__ embb,
    const float* __restrict__ whh,
    const float* __restrict__ decw, const float* __restrict__ decb,
    const float* __restrict__ outw, const float* __restrict__ outb,
    float* __restrict__ out, int B)
{
    __shared__ __align__(16) float sA [1024];
    __shared__ __align__(16) float sW1[1024];
    __shared__ __align__(16) float sWh[1024];
    __shared__ __align__(16) float sDec[160];
    __shared__ __align__(16) float sR[32];
    __shared__ __align__(16) float sEmbT[160];   // transposed: [k][l]
    __shared__ __align__(16) float sC1[32];
    __shared__ __align__(16) float sEmbB[32];
    __shared__ float sDecB[8];
    __shared__ float sOw[16];
    __shared__ float sOb[4];

    const int tid = threadIdx.x;
    for (int i = tid; i < 1024; i += 256){
        sA[i]  = g_A[i];
        sW1[i] = g_W1[i];
        sWh[i] = whh[i];
    }
    if (tid < 160){
        sDec[tid] = decw[tid];
        int l = tid / 5, k = tid % 5;
        sEmbT[k*32 + l] = embw[tid];
    }
    if (tid < 32){ sC1[tid] = g_c1[tid]; sR[tid] = g_r[tid]; sEmbB[tid] = embb[tid]; }
    if (tid < 15) sOw[tid] = outw[tid];
    if (tid < 5)  sDecB[tid] = decb[tid];
    if (tid < 3)  sOb[tid] = outb[tid];
    __syncthreads();

    int r = blockIdx.x * 256 + tid;
    if (r >= B) return;

    // ---- load x row (10 floats, 8B aligned) ----
    float xv[10];
    {
        const float2* xp = reinterpret_cast<const float2*>(x + (long long)r*10);
        #pragma unroll
        for (int k = 0; k < 5; k++){ float2 t = xp[k]; xv[2*k] = t.x; xv[2*k+1] = t.y; }
    }
    u64 xp0[5], xp1[5];
    #pragma unroll
    for (int k = 0; k < 5; k++){ xp0[k] = pack1(xv[k]); xp1[k] = pack1(xv[5+k]); }

    // ---- embedding (packed along output dims) ----
    u64 e0p[16], dep[16];
    const u64* ebp = reinterpret_cast<const u64*>(sEmbB);
    #pragma unroll
    for (int i = 0; i < 16; i++){
        u64 a0 = ebp[i], a1 = a0;
        #pragma unroll
        for (int k = 0; k < 5; k++){
            u64 w = *reinterpret_cast<const u64*>(sEmbT + k*32 + 2*i);
            a0 = fma2(w, xp0[k], a0);
            a1 = fma2(w, xp1[k], a1);
        }
        float v00, v10, v01, v11;
        unpack2(a0, v00, v10);
        unpack2(a1, v01, v11);
        float g00 = gelu1(v00), g10 = gelu1(v10);
        float g01 = gelu1(v01), g11 = gelu1(v11);
        e0p[i] = pack2(g00, g10);
        dep[i] = pack2(g01 - g00, g11 - g10);
    }

    // ---- attention: 4 accumulator chains per output pair ----
    u64 dE = 0ull, dD = 0ull, dR = 0ull;
    const u64* rp = reinterpret_cast<const u64*>(sR);
    #pragma unroll
    for (int i = 0; i < 16; i++){
        const ulonglong2* rowA0 = reinterpret_cast<const ulonglong2*>(sA + (2*i)*32);
        const ulonglong2* rowA1 = reinterpret_cast<const ulonglong2*>(sA + (2*i+1)*32);
        u64 w0a = 0ull, w0b = 0ull, w1a = 0ull, w1b = 0ull;
        #pragma unroll
        for (int c = 0; c < 4; c++){
            ulonglong2 v0 = rowA0[c],   v1 = rowA1[c];
            ulonglong2 u0 = rowA0[c+4], u1 = rowA1[c+4];
            w0a = fma2(v0.x, dep[2*c],   w0a);
            w0a = fma2(v0.y, dep[2*c+1], w0a);
            w1a = fma2(v1.x, dep[2*c],   w1a);
            w1a = fma2(v1.y, dep[2*c+1], w1a);
            w0b = fma2(u0.x, dep[2*c+8], w0b);
            w0b = fma2(u0.y, dep[2*c+9], w0b);
            w1b = fma2(u1.x, dep[2*c+8], w1b);
            w1b = fma2(u1.y, dep[2*c+9], w1b);
        }
        u64 wp = pack2(hadd2(add2(w0a, w0b)), hadd2(add2(w1a, w1b)));
        dE = fma2(e0p[i], wp, dE);
        dD = fma2(dep[i], wp, dD);
        dR = fma2(rp[i], dep[i], dR);
    }
    float d0 = hadd2(dE) + hadd2(dR);
    float d1 = d0 + hadd2(dD);
    float a01 = sig_hw(d0);
    float a11 = sig_hw(d1);
    u64 a01p = pack1(a01);
    u64 adp  = pack1(a11 - a01);

    // ---- m0 = e0 + a01*de (in place) ----
    #pragma unroll
    for (int i = 0; i < 16; i++) e0p[i] = fma2(a01p, dep[i], e0p[i]);

    // ---- h1 = tanh(W1 m0 + c1): 4 chains per output pair ----
    u64 h1p[16];
    #pragma unroll
    for (int i = 0; i < 16; i++){
        const ulonglong2* r0w = reinterpret_cast<const ulonglong2*>(sW1 + (2*i)*32);
        const ulonglong2* r1w = reinterpret_cast<const ulonglong2*>(sW1 + (2*i+1)*32);
        u64 s0a = 0ull, s0b = 0ull, s1a = 0ull, s1b = 0ull;
        #pragma unroll
        for (int c = 0; c < 4; c++){
            ulonglong2 v0 = r0w[c],   v1 = r1w[c];
            ulonglong2 u0 = r0w[c+4], u1 = r1w[c+4];
            s0a = fma2(v0.x, e0p[2*c],   s0a);
            s0a = fma2(v0.y, e0p[2*c+1], s0a);
            s1a = fma2(v1.x, e0p[2*c],   s1a);
            s1a = fma2(v1.y, e0p[2*c+1], s1a);
            s0b = fma2(u0.x, e0p[2*c+8], s0b);
            s0b = fma2(u0.y, e0p[2*c+9], s0b);
            s1b = fma2(u1.x, e0p[2*c+8], s1b);
            s1b = fma2(u1.y, e0p[2*c+9], s1b);
        }
        float v0 = hadd2(add2(s0a, s0b)) + sC1[2*i];
        float v1 = hadd2(add2(s1a, s1b)) + sC1[2*i+1];
        h1p[i] = pack2(tanh_hw(v0), tanh_hw(v1));
    }

    // ---- m1 = m0 + (a11-a01)*de (in place) ----
    #pragma unroll
    for (int i = 0; i < 16; i++) e0p[i] = fma2(adp, dep[i], e0p[i]);

    // ---- h2 = tanh(W1 m1 + Wh h1 + c1): 8 chains; write into dep ----
    #pragma unroll
    for (int i = 0; i < 16; i++){
        const ulonglong2* rw0 = reinterpret_cast<const ulonglong2*>(sW1 + (2*i)*32);
        const ulonglong2* rw1 = reinterpret_cast<const ulonglong2*>(sW1 + (2*i+1)*32);
        const ulonglong2* rh0 = reinterpret_cast<const ulonglong2*>(sWh + (2*i)*32);
        const ulonglong2* rh1 = reinterpret_cast<const ulonglong2*>(sWh + (2*i+1)*32);
        u64 s0a = 0ull, s0b = 0ull, s1a = 0ull, s1b = 0ull;
        u64 t0a = 0ull, t0b = 0ull, t1a = 0ull, t1b = 0ull;
        #pragma unroll
        for (int c = 0; c < 4; c++){
            ulonglong2 vw0 = rw0[c],   vh0 = rh0[c];
            ulonglong2 vw1 = rw1[c],   vh1 = rh1[c];
            ulonglong2 uw0 = rw0[c+4], uh0 = rh0[c+4];
            ulonglong2 uw1 = rw1[c+4], uh1 = rh1[c+4];
            s0a = fma2(vw0.x, e0p[2*c],   s0a);
            s0a = fma2(vw0.y, e0p[2*c+1], s0a);
            t0a = fma2(vh0.x, h1p[2*c],   t0a);
            t0a = fma2(vh0.y, h1p[2*c+1], t0a);
            s1a = fma2(vw1.x, e0p[2*c],   s1a);
            s1a = fma2(vw1.y, e0p[2*c+1], s1a);
            t1a = fma2(vh1.x, h1p[2*c],   t1a);
            t1a = fma2(vh1.y, h1p[2*c+1], t1a);
            s0b = fma2(uw0.x, e0p[2*c+8], s0b);
            s0b = fma2(uw0.y, e0p[2*c+9], s0b);
            t0b = fma2(uh0.x, h1p[2*c+8], t0b);
            t0b = fma2(uh0.y, h1p[2*c+9], t0b);
            s1b = fma2(uw1.x, e0p[2*c+8], s1b);
            s1b = fma2(uw1.y, e0p[2*c+9], s1b);
            t1b = fma2(uh1.x, h1p[2*c+8], t1b);
            t1b = fma2(uh1.y, h1p[2*c+9], t1b);
        }
        u64 sum0 = add2(add2(s0a, s0b), add2(t0a, t0b));
        u64 sum1 = add2(add2(s1a, s1b), add2(t1a, t1b));
        float v0 = hadd2(sum0) + sC1[2*i];
        float v1 = hadd2(sum1) + sC1[2*i+1];
        dep[i] = pack2(tanh_hw(v0), tanh_hw(v1));   // h2 -> dep
    }

    // ---- decode: d = gelu(Dec h2 + b) ; out = Ow d + ob ----
    float dv[5];
    #pragma unroll
    for (int j = 0; j < 5; j++){
        const ulonglong2* rd = reinterpret_cast<const ulonglong2*>(sDec + j*32);
        u64 acc = 0ull;
        #pragma unroll
        for (int c = 0; c < 8; c++){
            ulonglong2 v = rd[c];
            acc = fma2(v.x, dep[2*c],   acc);
            acc = fma2(v.y, dep[2*c+1], acc);
        }
        dv[j] = gelu1(hadd2(acc) + sDecB[j]);
    }
    #pragma unroll
    for (int o = 0; o < 3; o++){
        float acc = sOb[o];
        #pragma unroll
        for (int j = 0; j < 5; j++) acc = fmaf(sOw[o*5 + j], dv[j], acc);
        out[(long long)r*3 + o] = acc;
    }
}

// ---------------- launch ----------------
extern "C" void kernel_launch(void* const* d_in, const int* in_sizes, int n_in,
                              void* d_out, int out_size)
{
    const float* x      = (const float*)d_in[0];
    const float* embw   = (const float*)d_in[1];
    const float* embb   = (const float*)d_in[2];
    const float* ipw    = (const float*)d_in[3];
    const float* ipb    = (const float*)d_in[4];
    const float* opw    = (const float*)d_in[5];
    const float* opb    = (const float*)d_in[6];
    const float* wih    = (const float*)d_in[7];
    const float* bih    = (const float*)d_in[8];
    const float* whh    = (const float*)d_in[9];
    const float* bhh    = (const float*)d_in[10];
    const float* decw   = (const float*)d_in[11];
    const float* decb   = (const float*)d_in[12];
    const float* outw   = (const float*)d_in[13];
    const float* outb   = (const float*)d_in[14];
    float* out = (float*)d_out;

    int B = in_sizes[0] / 10;

    prep_kernel<<<1, 1024>>>(ipw, ipb, opw, opb, wih, bih, bhh);

    int blocks = (B + 255) / 256;
    fused_kernel<<<blocks, 256>>>(x, embw, embb, whh, decw, decb, outw, outb, out, B);
}

// round 17
// speedup vs baseline: 1.5125x; 1.0293x over previous
#include <cuda_runtime.h>
#include <math.h>

typedef unsigned long long u64;
typedef unsigned int u32;

// ---------------- packed f32x2 helpers ----------------
__device__ __forceinline__ u64 pack2(float a, float b){ u64 r; asm("mov.b64 %0,{%1,%2};":"=l"(r):"f"(a),"f"(b)); return r; }
__device__ __forceinline__ u64 pack1(float a){ u64 r; asm("mov.b64 %0,{%1,%1};":"=l"(r):"f"(a)); return r; }
__device__ __forceinline__ void unpack2(u64 v, float& a, float& b){ asm("mov.b64 {%0,%1},%2;":"=f"(a),"=f"(b):"l"(v)); }
__device__ __forceinline__ u64 fma2(u64 a,u64 b,u64 c){ u64 d; asm("fma.rn.f32x2 %0,%1,%2,%3;":"=l"(d):"l"(a),"l"(b),"l"(c)); return d; }
__device__ __forceinline__ float hadd2(u64 v){ float a,b; unpack2(v,a,b); return a+b; }

__device__ __forceinline__ float tanh_hw(float x){
    float y; asm("tanh.approx.f32 %0, %1;" : "=f"(y) : "f"(x)); return y;
}
__device__ __forceinline__ float sig_hw(float x){
    return fmaf(0.5f, tanh_hw(0.5f * x), 0.5f);
}
__device__ __forceinline__ float gelu1(float v){
    float u = (v * 0.7978845608028654f) * fmaf(0.044715f * v, v, 1.0f);
    float hv = 0.5f * v;
    return fmaf(hv, tanh_hw(u), hv);
}

// tf32 split: hi = round-to-nearest tf32 (as bits), lo = residual
__device__ __forceinline__ void tf32split(float x, u32& hi, u32& lo){
    u32 h; asm("cvt.rna.tf32.f32 %0, %1;" : "=r"(h) : "f"(x));
    hi = h;
    lo = __float_as_uint(x - __uint_as_float(h));
}

// warp-level tf32 MMA (baseline PTX, sm_80+; runs on tensor pipe)
__device__ __forceinline__ void mma1(float* c, u32 a0,u32 a1,u32 a2,u32 a3, u32 b0,u32 b1){
    asm volatile("mma.sync.aligned.m16n8k8.row.col.f32.tf32.tf32.f32 "
        "{%0,%1,%2,%3}, {%4,%5,%6,%7}, {%8,%9}, {%0,%1,%2,%3};"
        : "+f"(c[0]),"+f"(c[1]),"+f"(c[2]),"+f"(c[3])
        : "r"(a0),"r"(a1),"r"(a2),"r"(a3),"r"(b0),"r"(b1));
}

// ---------------- folded-weight scratch ----------------
__device__ float g_A[1024];   // (wq^T wk)/sqrt(32): w = de @ A^T
__device__ float g_W1[1024];  // w_ih @ Wo @ wv
__device__ float g_r[32];
__device__ float g_c1[32];

// ---------------- prep kernel (unchanged) ----------------
__global__ void prep_kernel(const float* __restrict__ ipw, const float* __restrict__ ipb,
                            const float* __restrict__ opw, const float* __restrict__ opb,
                            const float* __restrict__ wih, const float* __restrict__ bih,
                            const float* __restrict__ bhh)
{
    __shared__ float T[1024];
    __shared__ float t2[32];
    const float inv = 0.17677669529663688f;
    int tid = threadIdx.x;
    int i = tid >> 5, j = tid & 31;
    const float* wq = ipw;
    const float* wk = ipw + 1024;
    const float* wv = ipw + 2048;

    float a = 0.f, t = 0.f;
    #pragma unroll 8
    for (int m = 0; m < 32; m++){
        a += wq[m*32 + i] * wk[m*32 + j];
        t += opw[i*32 + m] * wv[m*32 + j];
    }
    g_A[i*32 + j] = a * inv;
    T[i*32 + j] = t;

    if (i == 0){
        float rr = 0.f, tt = 0.f;
        #pragma unroll 8
        for (int m = 0; m < 32; m++){
            rr += ipb[m] * wk[m*32 + j];
            tt += opw[j*32 + m] * ipb[64 + m];
        }
        g_r[j] = rr * inv;
        t2[j] = tt + opb[j];
    }
    __syncthreads();

    float w1 = 0.f;
    #pragma unroll 8
    for (int m = 0; m < 32; m++)
        w1 += wih[i*32 + m] * T[m*32 + j];
    g_W1[i*32 + j] = w1;

    if (i == 0){
        float c = 0.f;
        #pragma unroll 8
        for (int m = 0; m < 32; m++)
            c += wih[j*32 + m] * t2[m];
        g_c1[j] = c + bih[j] + bhh[j];
    }
}

// ---------------- SMEM layout (u32-word offsets), row stride 36 words ----------------
static constexpr int LDA = 36;
static constexpr int WOFF_ACT1_HI = 0;             // 256*36 = 9216 words each
static constexpr int WOFF_ACT1_LO = 9216;
static constexpr int WOFF_ACT2_HI = 18432;
static constexpr int WOFF_ACT2_LO = 27648;
static constexpr int WOFF_DST     = 36864;         // f32 staging, 9216 words
static constexpr int WOFF_WA_HI   = 46080;         // 32*36 = 1152 words each
static constexpr int WOFF_WA_LO   = 47232;
static constexpr int WOFF_W1_HI   = 48384;
static constexpr int WOFF_W1_LO   = 49536;
static constexpr int WOFF_WH_HI   = 50688;
static constexpr int WOFF_WH_LO   = 51840;
static constexpr int SMEM_WORDS   = 52992;
static constexpr int SMEM_BYTES   = SMEM_WORDS * 4;   // 211968

// store one row (32 floats, packed u64[16]) as tf32 hi/lo
__device__ __forceinline__ void store_act_pk(u32* hiB, u32* loB, const u64* v, int row){
    int base = row * LDA;
    #pragma unroll
    for (int j = 0; j < 8; j++){
        float f0,f1,f2,f3;
        unpack2(v[2*j],   f0, f1);
        unpack2(v[2*j+1], f2, f3);
        u32 h0,h1,h2,h3,l0,l1,l2,l3;
        tf32split(f0,h0,l0); tf32split(f1,h1,l1);
        tf32split(f2,h2,l2); tf32split(f3,h3,l3);
        *(uint4*)&hiB[base + 4*j] = make_uint4(h0,h1,h2,h3);
        *(uint4*)&loB[base + 4*j] = make_uint4(l0,l1,l2,l3);
    }
}
__device__ __forceinline__ void store_act_f32(u32* hiB, u32* loB, const float* v, int row){
    int base = row * LDA;
    #pragma unroll
    for (int j = 0; j < 8; j++){
        u32 h0,h1,h2,h3,l0,l1,l2,l3;
        tf32split(v[4*j+0],h0,l0); tf32split(v[4*j+1],h1,l1);
        tf32split(v[4*j+2],h2,l2); tf32split(v[4*j+3],h3,l3);
        *(uint4*)&hiB[base + 4*j] = make_uint4(h0,h1,h2,h3);
        *(uint4*)&loB[base + 4*j] = make_uint4(l0,l1,l2,l3);
    }
}

// warp-local 32x32x32 GEMM with 3-pass tf32 compensation; accumulates into c
__device__ __forceinline__ void warp_gemm(float c[2][4][4], const u32* __restrict__ dsm,
                                          int actHi, int actLo, int wHi, int wLo,
                                          int R, int lane)
{
    const int g = lane >> 2, t = lane & 3;
    #pragma unroll
    for (int m = 0; m < 2; m++){
        int rowa = (R + 16*m + g) * LDA + t;
        #pragma unroll
        for (int k = 0; k < 4; k++){
            int pa = rowa + 8*k;
            u32 a0h = dsm[actHi + pa];
            u32 a1h = dsm[actHi + pa + 8*LDA];
            u32 a2h = dsm[actHi + pa + 4];
            u32 a3h = dsm[actHi + pa + 8*LDA + 4];
            u32 a0l = dsm[actLo + pa];
            u32 a1l = dsm[actLo + pa + 8*LDA];
            u32 a2l = dsm[actLo + pa + 4];
            u32 a3l = dsm[actLo + pa + 8*LDA + 4];
            #pragma unroll
            for (int n = 0; n < 4; n++){
                int pb = (8*n + g) * LDA + t + 8*k;
                u32 b0h = dsm[wHi + pb], b1h = dsm[wHi + pb + 4];
                u32 b0l = dsm[wLo + pb], b1l = dsm[wLo + pb + 4];
                mma1(c[m][n], a0h,a1h,a2h,a3h, b0h,b1h);
                mma1(c[m][n], a0h,a1h,a2h,a3h, b0l,b1l);
                mma1(c[m][n], a0l,a1l,a2l,a3l, b0h,b1h);
            }
        }
    }
}

__device__ __forceinline__ void dst_write(const float c[2][4][4], float* D, int R, int lane){
    const int g = lane >> 2, t = lane & 3;
    #pragma unroll
    for (int m = 0; m < 2; m++){
        int r0 = (R + 16*m + g) * LDA;
        #pragma unroll
        for (int n = 0; n < 4; n++){
            int a = r0 + 8*n + 2*t;                 // even word -> 8B aligned
            *(float2*)&D[a]           = make_float2(c[m][n][0], c[m][n][1]);
            *(float2*)&D[a + 8*LDA]   = make_float2(c[m][n][2], c[m][n][3]);
        }
    }
}

// ---------------- fused main: 256 rows/CTA; warp-local tf32 mma GEMMs ----------------
__global__ __launch_bounds__(256) void fused_kernel(
    const float* __restrict__ x,
    const float* __restrict__ embw, const float* __restrict__ embb,
    const float* __restrict__ whh,
    const float* __restrict__ decw, const float* __restrict__ decb,
    const float* __restrict__ outw, const float* __restrict__ outb,
    float* __restrict__ out, int B)
{
    extern __shared__ u32 dsm[];
    float* dsmF = (float*)dsm;

    __shared__ __align__(16) float sEmbT[160];
    __shared__ __align__(16) float sC1[32];
    __shared__ __align__(16) float sR[32];
    __shared__ __align__(16) float sEmbB[32];
    __shared__ __align__(16) float sDec[160];
    __shared__ float sDecB[8];
    __shared__ float sOw[16];
    __shared__ float sOb[4];

    const int tid  = threadIdx.x;
    const int lane = tid & 31;
    const int wid  = tid >> 5;
    const int R    = wid * 32;

    // ---- prologue: weights -> SMEM (tf32 hi/lo, row-major [n][k] stride 36) ----
    for (int i = tid; i < 1024; i += 256){
        int n = i >> 5, k = i & 31;
        int a = n*LDA + k;
        u32 h, l;
        tf32split(g_A[i],  h, l); dsm[WOFF_WA_HI + a] = h; dsm[WOFF_WA_LO + a] = l;
        tf32split(g_W1[i], h, l); dsm[WOFF_W1_HI + a] = h; dsm[WOFF_W1_LO + a] = l;
        tf32split(whh[i],  h, l); dsm[WOFF_WH_HI + a] = h; dsm[WOFF_WH_LO + a] = l;
    }
    if (tid < 160){
        sDec[tid] = decw[tid];
        int l = tid / 5, k = tid % 5;
        sEmbT[k*32 + l] = embw[tid];
    }
    if (tid < 32){ sC1[tid] = g_c1[tid]; sR[tid] = g_r[tid]; sEmbB[tid] = embb[tid]; }
    if (tid < 15) sOw[tid] = outw[tid];
    if (tid < 5)  sDecB[tid] = decb[tid];
    if (tid < 3)  sOb[tid] = outb[tid];
    __syncthreads();

    long long r = (long long)blockIdx.x * 256 + tid;
    long long rc = (r < (long long)B) ? r : (long long)B - 1;

    // ---- embedding (fp32, packed) ----
    float xv[10];
    {
        const float2* xp = reinterpret_cast<const float2*>(x + rc*10);
        #pragma unroll
        for (int k = 0; k < 5; k++){ float2 t = xp[k]; xv[2*k] = t.x; xv[2*k+1] = t.y; }
    }
    u64 xp0[5], xp1[5];
    #pragma unroll
    for (int k = 0; k < 5; k++){ xp0[k] = pack1(xv[k]); xp1[k] = pack1(xv[5+k]); }

    u64 e0p[16], dep[16];
    const u64* ebp = reinterpret_cast<const u64*>(sEmbB);
    #pragma unroll
    for (int i = 0; i < 16; i++){
        u64 a0 = ebp[i], a1 = a0;
        #pragma unroll
        for (int k = 0; k < 5; k++){
            u64 w = *(const u64*)(sEmbT + k*32 + 2*i);
            a0 = fma2(w, xp0[k], a0);
            a1 = fma2(w, xp1[k], a1);
        }
        float v00, v10, v01, v11;
        unpack2(a0, v00, v10);
        unpack2(a1, v01, v11);
        float g00 = gelu1(v00), g10 = gelu1(v10);
        float g01 = gelu1(v01), g11 = gelu1(v11);
        e0p[i] = pack2(g00, g10);
        dep[i] = pack2(g01 - g00, g11 - g10);
    }

    // ======== stage 1: w = de @ A^T ========
    store_act_pk(dsm + WOFF_ACT1_HI, dsm + WOFF_ACT1_LO, dep, tid);
    __syncwarp();
    {
        float c[2][4][4];
        #pragma unroll
        for (int m = 0; m < 2; m++)
            #pragma unroll
            for (int n = 0; n < 4; n++)
                #pragma unroll
                for (int q = 0; q < 4; q++) c[m][n][q] = 0.f;
        warp_gemm(c, dsm, WOFF_ACT1_HI, WOFF_ACT1_LO, WOFF_WA_HI, WOFF_WA_LO, R, lane);
        dst_write(c, dsmF + WOFF_DST, R, lane);
    }
    __syncwarp();

    u64 wreg[16];
    {
        const ulonglong2* p = (const ulonglong2*)&dsmF[WOFF_DST + tid*LDA];
        #pragma unroll
        for (int i = 0; i < 8; i++){ ulonglong2 v = p[i]; wreg[2*i] = v.x; wreg[2*i+1] = v.y; }
    }

    // ---- dots -> attention coefficients ----
    u64 dE = 0ull, dD = 0ull, dR = 0ull;
    const u64* rp = reinterpret_cast<const u64*>(sR);
    #pragma unroll
    for (int i = 0; i < 16; i++){
        dE = fma2(e0p[i], wreg[i], dE);
        dD = fma2(dep[i], wreg[i], dD);
        dR = fma2(rp[i], dep[i], dR);
    }
    float d0 = hadd2(dE) + hadd2(dR);
    float d1 = d0 + hadd2(dD);
    float a01 = sig_hw(d0);
    float a11 = sig_hw(d1);
    u64 a01p = pack1(a01);
    u64 adp  = pack1(a11 - a01);

    // m0 = e0 + a01*de
    #pragma unroll
    for (int i = 0; i < 16; i++) e0p[i] = fma2(a01p, dep[i], e0p[i]);

    // ======== stage 2: h1pre = m0 @ W1^T ========
    store_act_pk(dsm + WOFF_ACT1_HI, dsm + WOFF_ACT1_LO, e0p, tid);
    __syncwarp();
    {
        float c[2][4][4];
        #pragma unroll
        for (int m = 0; m < 2; m++)
            #pragma unroll
            for (int n = 0; n < 4; n++)
                #pragma unroll
                for (int q = 0; q < 4; q++) c[m][n][q] = 0.f;
        warp_gemm(c, dsm, WOFF_ACT1_HI, WOFF_ACT1_LO, WOFF_W1_HI, WOFF_W1_LO, R, lane);
        dst_write(c, dsmF + WOFF_DST, R, lane);
    }
    __syncwarp();

    float h1f[32];
    {
        const float* p = &dsmF[WOFF_DST + tid*LDA];
        #pragma unroll
        for (int i = 0; i < 32; i++) h1f[i] = tanh_hw(p[i] + sC1[i]);
    }
    store_act_f32(dsm + WOFF_ACT2_HI, dsm + WOFF_ACT2_LO, h1f, tid);

    // m1 = m0 + (a11-a01)*de
    #pragma unroll
    for (int i = 0; i < 16; i++) e0p[i] = fma2(adp, dep[i], e0p[i]);
    store_act_pk(dsm + WOFF_ACT1_HI, dsm + WOFF_ACT1_LO, e0p, tid);
    __syncwarp();

    // ======== stage 3: h2pre = m1 @ W1^T + h1 @ Wh^T ========
    {
        float c[2][4][4];
        #pragma unroll
        for (int m = 0; m < 2; m++)
            #pragma unroll
            for (int n = 0; n < 4; n++)
                #pragma unroll
                for (int q = 0; q < 4; q++) c[m][n][q] = 0.f;
        warp_gemm(c, dsm, WOFF_ACT1_HI, WOFF_ACT1_LO, WOFF_W1_HI, WOFF_W1_LO, R, lane);
        warp_gemm(c, dsm, WOFF_ACT2_HI, WOFF_ACT2_LO, WOFF_WH_HI, WOFF_WH_LO, R, lane);
        dst_write(c, dsmF + WOFF_DST, R, lane);
    }
    __syncwarp();

    u64 h2p[16];
    {
        const float* p = &dsmF[WOFF_DST + tid*LDA];
        #pragma unroll
        for (int i = 0; i < 16; i++){
            float v0 = tanh_hw(p[2*i]   + sC1[2*i]);
            float v1 = tanh_hw(p[2*i+1] + sC1[2*i+1]);
            h2p[i] = pack2(v0, v1);
        }
    }

    // ---- decode ----
    float dv[5];
    #pragma unroll
    for (int j = 0; j < 5; j++){
        const ulonglong2* rd = reinterpret_cast<const ulonglong2*>(sDec + j*32);
        u64 acc = 0ull;
        #pragma unroll
        for (int c = 0; c < 8; c++){
            ulonglong2 v = rd[c];
            acc = fma2(v.x, h2p[2*c],   acc);
            acc = fma2(v.y, h2p[2*c+1], acc);
        }
        dv[j] = gelu1(hadd2(acc) + sDecB[j]);
    }
    if (r < (long long)B){
        #pragma unroll
        for (int o = 0; o < 3; o++){
            float acc = sOb[o];
            #pragma unroll
            for (int j = 0; j < 5; j++) acc = fmaf(sOw[o*5 + j], dv[j], acc);
            out[r*3 + o] = acc;
        }
    }
}

// ---------------- launch ----------------
extern "C" void kernel_launch(void* const* d_in, const int* in_sizes, int n_in,
                              void* d_out, int out_size)
{
    const float* x      = (const float*)d_in[0];
    const float* embw   = (const float*)d_in[1];
    const float* embb   = (const float*)d_in[2];
    const float* ipw    = (const float*)d_in[3];
    const float* ipb    = (const float*)d_in[4];
    const float* opw    = (const float*)d_in[5];
    const float* opb    = (const float*)d_in[6];
    const float* wih    = (const float*)d_in[7];
    const float* bih    = (const float*)d_in[8];
    const float* whh    = (const float*)d_in[9];
    const float* bhh    = (const float*)d_in[10];
    const float* decw   = (const float*)d_in[11];
    const float* decb   = (const float*)d_in[12];
    const float* outw   = (const float*)d_in[13];
    const float* outb   = (const float*)d_in[14];
    float* out = (float*)d_out;

    int B = in_sizes[0] / 10;

    cudaFuncSetAttribute(fused_kernel, cudaFuncAttributeMaxDynamicSharedMemorySize, SMEM_BYTES);

    prep_kernel<<<1, 1024>>>(ipw, ipb, opw, opb, wih, bih, bhh);

    int blocks = (B + 255) / 256;
    fused_kernel<<<blocks, 256, SMEM_BYTES>>>(x, embw, embb, whh, decw, decb, outw, outb, out, B);
}